// round 2
// baseline (speedup 1.0000x reference)
#include <cuda_runtime.h>
#include <cuda_bf16.h>
#include <cstdint>

// ======================= problem constants =======================
#define DIMX     64
#define HIDX     256
#define NSTEPS   32
#define MTILE    128
#define NTHREADS 256

// ======================= SMEM layout (bytes) =====================
#define SM_B1   0
#define SM_TW1  1024
#define SM_B2   2048
#define SM_B3   3072
#define SM_W1   4096      // 256n x 64k bf16, 128B rows, SW128    (32768 B)
#define SM_W2   36864     // 4 k-chunks x (256n x 64k)            (131072 B)
#define SM_W3   167936    // 4 k-chunks x (64n x 64k)             (32768 B)
#define SMEM_BYTES 200704

#define SWZ(off) ((off) ^ (((off) >> 3) & 0x70))

// ======================= device helpers ==========================
__device__ __forceinline__ uint32_t smem_to_u32(const void* p) {
    uint32_t a;
    asm("{ .reg .u64 t; cvta.to.shared.u64 t, %1; cvt.u32.u64 %0, t; }" : "=r"(a) : "l"(p));
    return a;
}
__device__ __forceinline__ uint32_t pack_bf16x2(float lo, float hi) {
    uint32_t r;
    asm("cvt.rn.bf16x2.f32 %0, %1, %2;" : "=r"(r) : "f"(hi), "f"(lo));
    return r;
}
__device__ __forceinline__ float fast_tanh(float x) {
    float y;
    asm("tanh.approx.f32 %0, %1;" : "=f"(y) : "f"(x));
    return y;
}
__device__ __forceinline__ float silu(float a) {
    // a * sigmoid(a) = a * 0.5*(1 + tanh(a/2)); tanh.approx = 1 MUFU op
    return a * (0.5f * fast_tanh(0.5f * a) + 0.5f);
}
__device__ __forceinline__ void ldsm4(uint32_t& r0, uint32_t& r1, uint32_t& r2, uint32_t& r3,
                                      uint32_t addr) {
    asm volatile("ldmatrix.sync.aligned.m8n8.x4.shared.b16 {%0,%1,%2,%3}, [%4];"
                 : "=r"(r0), "=r"(r1), "=r"(r2), "=r"(r3) : "r"(addr));
}
__device__ __forceinline__ void mma_bf16(float* c, const uint32_t* a, uint32_t b0, uint32_t b1) {
    asm volatile("mma.sync.aligned.m16n8k16.row.col.f32.bf16.bf16.f32 "
                 "{%0,%1,%2,%3}, {%4,%5,%6,%7}, {%8,%9}, {%0,%1,%2,%3};"
                 : "+f"(c[0]), "+f"(c[1]), "+f"(c[2]), "+f"(c[3])
                 : "r"(a[0]), "r"(a[1]), "r"(a[2]), "r"(a[3]), "r"(b0), "r"(b1));
}

// ======================= kernel ==================================
__global__ void __launch_bounds__(NTHREADS, 1) flow_kernel(
    const float* __restrict__ x0, const float* __restrict__ W1,
    const float* __restrict__ b1, const float* __restrict__ W2,
    const float* __restrict__ b2, const float* __restrict__ W3,
    const float* __restrict__ b3, float* __restrict__ out)
{
    extern __shared__ char smem[];
    const uint32_t sbase = smem_to_u32(smem);
    const int tid  = threadIdx.x;
    const int wid  = tid >> 5;
    const int lane = tid & 31;

    float* sb1  = (float*)(smem + SM_B1);
    float* stw1 = (float*)(smem + SM_TW1);
    float* sb2  = (float*)(smem + SM_B2);
    float* sb3  = (float*)(smem + SM_B3);

    // ---------------- prologue: biases ----------------
    for (int i = tid; i < HIDX; i += NTHREADS) {
        sb1[i]  = b1[i];
        stw1[i] = W1[DIMX * HIDX + i];   // t-row of W1
        sb2[i]  = b2[i];
    }
    if (tid < DIMX) sb3[tid] = b3[tid];

    // ---------------- prologue: weights -> bf16, W^T layout (n rows, k contig), SW128 ----
    for (int idx = tid; idx < DIMX * HIDX; idx += NTHREADS) {          // W1 (64k,256n)
        int k = idx >> 8, n = idx & 255;
        uint32_t off = (uint32_t)(n * 128 + k * 2);
        *(__nv_bfloat16*)(smem + SM_W1 + SWZ(off)) = __float2bfloat16(W1[idx]);
    }
    for (int idx = tid; idx < HIDX * HIDX; idx += NTHREADS) {          // W2 (256k,256n)
        int k = idx >> 8, n = idx & 255;
        int c = k >> 6, kk = k & 63;
        uint32_t off = (uint32_t)(n * 128 + kk * 2);
        *(__nv_bfloat16*)(smem + SM_W2 + c * 32768 + SWZ(off)) = __float2bfloat16(W2[idx]);
    }
    for (int idx = tid; idx < HIDX * DIMX; idx += NTHREADS) {          // W3 (256k,64n)
        int k = idx >> 6, n = idx & 63;
        int c = k >> 6, kk = k & 63;
        uint32_t off = (uint32_t)(n * 128 + kk * 2);
        *(__nv_bfloat16*)(smem + SM_W3 + c * 8192 + SWZ(off)) = __float2bfloat16(W3[idx]);
    }
    __syncthreads();

    // ---------------- per-lane ldmatrix addressing ----------------
    // x4 tiles: g=0 -> (n0..n0+7, k0..k0+7)   = b0 of n-tile0
    //           g=1 -> (n0..n0+7, k0+8..+15)  = b1 of n-tile0
    //           g=2 -> (n0+8.., k0..)         = b0 of n-tile1
    //           g=3 -> (n0+8.., k0+8..)       = b1 of n-tile1
    const int r = lane & 7, g = lane >> 3;
    const uint32_t ld_row = (uint32_t)((r + ((g >> 1) << 3)) * 128);
    const uint32_t g1 = (uint32_t)(g & 1);
    // per-ldmatrix lane addr = chunk_base + n0*128 + ld_row + ((((kt<<1)|g1) ^ r) << 4)

    // ---------------- load x (fp32, C-fragment layout) ----------------
    const int  m0   = wid * 16;
    const long rowA = (long)blockIdx.x * MTILE + m0 + (lane >> 2);
    const long rowB = rowA + 8;
    const int  q2   = (lane & 3) * 2;

    float x[32];   // n-tile t: x[4t+{0,1}] rows rowA cols 8t+q2,+1 ; x[4t+{2,3}] rows rowB
    #pragma unroll
    for (int t = 0; t < 8; t++) {
        float2 pa = *(const float2*)(x0 + rowA * DIMX + t * 8 + q2);
        float2 pb = *(const float2*)(x0 + rowB * DIMX + t * 8 + q2);
        x[4 * t + 0] = pa.x; x[4 * t + 1] = pa.y;
        x[4 * t + 2] = pb.x; x[4 * t + 3] = pb.y;
    }

    const float dt = 1.0f / NSTEPS;
    uint32_t hA[64];   // GEMM2 A fragments: 16 k-tiles x {a0,a1,a2,a3}

    for (int s = 0; s < NSTEPS; s++) {
        const float tval = ((float)s + 0.5f) * dt;

        // ---- x -> A fragments (bf16) for GEMM1 ----
        uint32_t xA[16];
        #pragma unroll
        for (int j = 0; j < 4; j++) {
            xA[4 * j + 0] = pack_bf16x2(x[8 * j + 0], x[8 * j + 1]);
            xA[4 * j + 1] = pack_bf16x2(x[8 * j + 2], x[8 * j + 3]);
            xA[4 * j + 2] = pack_bf16x2(x[8 * j + 4], x[8 * j + 5]);
            xA[4 * j + 3] = pack_bf16x2(x[8 * j + 6], x[8 * j + 7]);
        }

        // ================= GEMM1: h = silu(x@W1 + b1 + t*tw1)  (N=256,K=64) =========
        #pragma unroll
        for (int pair = 0; pair < 16; pair++) {        // 16 n-tile pairs (16 cols each)
            float C[8] = {0, 0, 0, 0, 0, 0, 0, 0};
            const uint32_t base = sbase + SM_W1 + (uint32_t)(pair * 16 * 128) + ld_row;
            #pragma unroll
            for (int kt = 0; kt < 4; kt++) {
                uint32_t w0, w1_, w2_, w3_;
                ldsm4(w0, w1_, w2_, w3_, base + ((((uint32_t)(kt << 1) | g1) ^ (uint32_t)r) << 4));
                mma_bf16(C,     xA + 4 * kt, w0,  w1_);
                mma_bf16(C + 4, xA + 4 * kt, w2_, w3_);
            }
            const int col0 = pair * 16 + q2;
            float2 bA = *(const float2*)(sb1 + col0);
            float2 tA = *(const float2*)(stw1 + col0);
            float2 bB = *(const float2*)(sb1 + col0 + 8);
            float2 tB = *(const float2*)(stw1 + col0 + 8);
            float biasAx = fmaf(tval, tA.x, bA.x), biasAy = fmaf(tval, tA.y, bA.y);
            float biasBx = fmaf(tval, tB.x, bB.x), biasBy = fmaf(tval, tB.y, bB.y);
            float h0 = silu(C[0] + biasAx), h1 = silu(C[1] + biasAy);
            float h2 = silu(C[2] + biasAx), h3 = silu(C[3] + biasAy);
            float h4 = silu(C[4] + biasBx), h5 = silu(C[5] + biasBy);
            float h6 = silu(C[6] + biasBx), h7 = silu(C[7] + biasBy);
            hA[pair * 4 + 0] = pack_bf16x2(h0, h1);
            hA[pair * 4 + 1] = pack_bf16x2(h2, h3);
            hA[pair * 4 + 2] = pack_bf16x2(h4, h5);
            hA[pair * 4 + 3] = pack_bf16x2(h6, h7);
        }

        // ============ GEMM2 (N=256,K=256) fused with GEMM3 (N=64,K=256) ============
        float v[32] = {0};   // GEMM3 accumulators, same layout as x
        #pragma unroll
        for (int c = 0; c < 4; c++) {                  // 64-col chunk of hidden2
            float C2[32];
            #pragma unroll
            for (int i = 0; i < 32; i++) C2[i] = 0.0f;

            #pragma unroll
            for (int kc = 0; kc < 4; kc++) {           // k-chunks of W2
                const uint32_t cb = sbase + SM_W2 + (uint32_t)(kc * 32768) + ld_row;
                #pragma unroll
                for (int kt = 0; kt < 4; kt++) {
                    const uint32_t koff = ((((uint32_t)(kt << 1) | g1) ^ (uint32_t)r) << 4);
                    const uint32_t* a = hA + (kc * 4 + kt) * 4;
                    #pragma unroll
                    for (int p = 0; p < 4; p++) {
                        uint32_t w0, w1_, w2_, w3_;
                        ldsm4(w0, w1_, w2_, w3_,
                              cb + (uint32_t)((c * 64 + p * 16) * 128) + koff);
                        mma_bf16(C2 + p * 8,     a, w0,  w1_);
                        mma_bf16(C2 + p * 8 + 4, a, w2_, w3_);
                    }
                }
            }

            // ---- epilogue: g = silu(C2 + b2) -> A fragments for GEMM3 k-slice ----
            uint32_t gA[16];
            #pragma unroll
            for (int p = 0; p < 4; p++) {
                const int col0 = c * 64 + p * 16 + q2;
                float2 bA = *(const float2*)(sb2 + col0);
                float2 bB = *(const float2*)(sb2 + col0 + 8);
                float h0 = silu(C2[p * 8 + 0] + bA.x), h1 = silu(C2[p * 8 + 1] + bA.y);
                float h2 = silu(C2[p * 8 + 2] + bA.x), h3 = silu(C2[p * 8 + 3] + bA.y);
                float h4 = silu(C2[p * 8 + 4] + bB.x), h5 = silu(C2[p * 8 + 5] + bB.y);
                float h6 = silu(C2[p * 8 + 6] + bB.x), h7 = silu(C2[p * 8 + 7] + bB.y);
                gA[p * 4 + 0] = pack_bf16x2(h0, h1);
                gA[p * 4 + 1] = pack_bf16x2(h2, h3);
                gA[p * 4 + 2] = pack_bf16x2(h4, h5);
                gA[p * 4 + 3] = pack_bf16x2(h6, h7);
            }

            // ---- GEMM3 partial: v += g @ W3[k-slice]  (k-tiles p=0..3) ----
            const uint32_t cb3 = sbase + SM_W3 + (uint32_t)(c * 8192) + ld_row;
            #pragma unroll
            for (int p = 0; p < 4; p++) {
                const uint32_t koff = ((((uint32_t)(p << 1) | g1) ^ (uint32_t)r) << 4);
                #pragma unroll
                for (int ntp = 0; ntp < 4; ntp++) {
                    uint32_t w0, w1_, w2_, w3_;
                    ldsm4(w0, w1_, w2_, w3_, cb3 + (uint32_t)(ntp * 16 * 128) + koff);
                    mma_bf16(v + ntp * 8,     gA + p * 4, w0,  w1_);
                    mma_bf16(v + ntp * 8 + 4, gA + p * 4, w2_, w3_);
                }
            }
        }

        // ---- x += dt * (v + b3) ----
        #pragma unroll
        for (int t = 0; t < 8; t++) {
            float2 p3 = *(const float2*)(sb3 + t * 8 + q2);
            x[4 * t + 0] += dt * (v[4 * t + 0] + p3.x);
            x[4 * t + 1] += dt * (v[4 * t + 1] + p3.y);
            x[4 * t + 2] += dt * (v[4 * t + 2] + p3.x);
            x[4 * t + 3] += dt * (v[4 * t + 3] + p3.y);
        }
    }

    // ---------------- store result ----------------
    #pragma unroll
    for (int t = 0; t < 8; t++) {
        *(float2*)(out + rowA * DIMX + t * 8 + q2) = make_float2(x[4 * t + 0], x[4 * t + 1]);
        *(float2*)(out + rowB * DIMX + t * 8 + q2) = make_float2(x[4 * t + 2], x[4 * t + 3]);
    }
}

// ======================= launch ==================================
extern "C" void kernel_launch(void* const* d_in, const int* in_sizes, int n_in,
                              void* d_out, int out_size) {
    const float* x0 = (const float*)d_in[0];
    const float* W1 = (const float*)d_in[1];
    const float* b1 = (const float*)d_in[2];
    const float* W2 = (const float*)d_in[3];
    const float* b2 = (const float*)d_in[4];
    const float* W3 = (const float*)d_in[5];
    const float* b3 = (const float*)d_in[6];
    float* out = (float*)d_out;

    const int nrows = in_sizes[0] / DIMX;
    const int grid  = nrows / MTILE;

    cudaFuncSetAttribute(flow_kernel, cudaFuncAttributeMaxDynamicSharedMemorySize, SMEM_BYTES);
    flow_kernel<<<grid, NTHREADS, SMEM_BYTES>>>(x0, W1, b1, W2, b2, W3, b3, out);
}